// round 1
// baseline (speedup 1.0000x reference)
#include <cuda_runtime.h>
#include <cuda_bf16.h>

// Problem constants (validated against in_sizes at launch by size-matching).
#define NN 200000
#define EE 6400000
// R=3, B=5, H=16, C=8

// ---------------- scratch (device globals; no allocation allowed) -----------
__device__ float4 g_xw1   [3 * NN * 4];   // [r][n][16] bf layer1 messages
__device__ float4 g_sums1 [3 * NN * 4];   // per (r,dst) sums, layer1
__device__ float4 g_rootx1[NN * 4];       // x@root1 + bias1
__device__ float4 g_h     [NN * 4];       // layer1 output (post relu)
__device__ float4 g_xw2   [3 * NN * 2];   // [r][n][8] layer2 messages
__device__ float4 g_sums2 [3 * NN * 2];   // per (r,dst) sums, layer2
__device__ float4 g_rootx2[NN * 2];       // h@root2 + bias2
__device__ float4 g_cnt4  [3 * NN / 4];   // edge counts per (r,dst), float
__device__ float  g_W1[3 * 3 * 16];       // comp1 x basis1
__device__ float  g_W2[3 * 16 * 8];       // comp2 x basis2

// ---------------- vectorized global reductions ------------------------------
__device__ __forceinline__ void red_add_v4(float4* addr, float4 v) {
    asm volatile("red.relaxed.gpu.global.add.v4.f32 [%0], {%1,%2,%3,%4};"
                 :: "l"(addr), "f"(v.x), "f"(v.y), "f"(v.z), "f"(v.w) : "memory");
}
__device__ __forceinline__ void red_add_f32(float* addr, float v) {
    asm volatile("red.relaxed.gpu.global.add.f32 [%0], %1;"
                 :: "l"(addr), "f"(v) : "memory");
}

// ---------------- kernels ---------------------------------------------------

// Zero all accumulators (graph-replay determinism).
__global__ void zero_all() {
    const int NS1 = 3 * NN * 4;        // 2,400,000 float4
    const int NS2 = 3 * NN * 2;        // 1,200,000
    const int NC  = 3 * NN / 4;        //   150,000
    int i = blockIdx.x * blockDim.x + threadIdx.x;
    float4 z = make_float4(0.f, 0.f, 0.f, 0.f);
    if (i < NS1)                 g_sums1[i] = z;
    else if (i < NS1 + NS2)      g_sums2[i - NS1] = z;
    else if (i < NS1 + NS2 + NC) g_cnt4[i - NS1 - NS2] = z;
}

// W[r] = sum_b comp[r,b] * basis[b]   (tiny)
__global__ void prep_W(const float* __restrict__ b1, const float* __restrict__ c1,
                       const float* __restrict__ b2, const float* __restrict__ c2) {
    int t = threadIdx.x;
    if (t < 144) {  // W1: [r][i][o], i<3, o<16
        int r = t / 48, rem = t % 48, i = rem / 16, o = rem % 16;
        float acc = 0.f;
        #pragma unroll
        for (int b = 0; b < 5; b++) acc += c1[r * 5 + b] * b1[(b * 3 + i) * 16 + o];
        g_W1[t] = acc;
    }
    if (t < 384) {  // W2: [r][k][c], k<16, c<8
        int r = t / 128, rem = t % 128, k = rem / 8, c = rem % 8;
        float acc = 0.f;
        #pragma unroll
        for (int b = 0; b < 5; b++) acc += c2[r * 5 + b] * b2[(b * 16 + k) * 8 + c];
        g_W2[t] = acc;
    }
}

// Layer-1 dense part: xw1[r][n][o] = x[n]·W1[r][:,o];  rootx1 = x@root1 + bias1
__global__ void dense1(const float* __restrict__ x, const float* __restrict__ root1,
                       const float* __restrict__ bias1) {
    int gid = blockIdx.x * blockDim.x + threadIdx.x;
    if (gid >= NN * 16) return;
    int n = gid >> 4, o = gid & 15;
    float x0 = x[n * 3 + 0], x1 = x[n * 3 + 1], x2 = x[n * 3 + 2];
    float* xw1 = (float*)g_xw1;
    #pragma unroll
    for (int r = 0; r < 3; r++) {
        float v = x0 * g_W1[r * 48 + o] + x1 * g_W1[r * 48 + 16 + o]
                + x2 * g_W1[r * 48 + 32 + o];
        xw1[(r * NN + n) * 16 + o] = v;
    }
    ((float*)g_rootx1)[gid] =
        x0 * root1[o] + x1 * root1[16 + o] + x2 * root1[32 + o] + bias1[o];
}

// Layer-1 edge scatter: 4 threads/edge, each one float4; counts fused on lane c==0.
__global__ void scatter1(const int* __restrict__ src, const int* __restrict__ dst,
                         const int* __restrict__ et) {
    int gid = blockIdx.x * blockDim.x + threadIdx.x;
    if (gid >= EE * 4) return;
    int e = gid >> 2, c = gid & 3;
    int r = et[e], s = src[e], d = dst[e];
    float4 v = __ldg(&g_xw1[(r * NN + s) * 4 + c]);
    red_add_v4(&g_sums1[(r * NN + d) * 4 + c], v);
    if (c == 0) red_add_f32(&((float*)g_cnt4)[r * NN + d], 1.0f);
}

// Layer-1 finalize: h = relu( sum_r sums1/cnt + rootx1 )
__global__ void finalize1() {
    int gid = blockIdx.x * blockDim.x + threadIdx.x;
    if (gid >= NN * 16) return;
    int n = gid >> 4;
    int o = gid & 15; (void)o;
    float acc = ((float*)g_rootx1)[gid];
    const float* cnt = (const float*)g_cnt4;
    const float* s1 = (const float*)g_sums1;
    #pragma unroll
    for (int r = 0; r < 3; r++) {
        float inv = 1.0f / fmaxf(cnt[r * NN + n], 1.0f);
        acc += s1[(r * NN + n) * 16 + (gid & 15)] * inv;
    }
    ((float*)g_h)[gid] = fmaxf(acc, 0.0f);
}

// Layer-2 dense part: xw2[r][n][c] = h[n]·W2[r][:,c]; rootx2 = h@root2 + bias2
__global__ void dense2(const float* __restrict__ root2, const float* __restrict__ bias2) {
    int gid = blockIdx.x * blockDim.x + threadIdx.x;
    if (gid >= NN * 8) return;
    int n = gid >> 3, c = gid & 7;
    float hv[16];
    #pragma unroll
    for (int q = 0; q < 4; q++) {
        float4 t = g_h[n * 4 + q];
        hv[q * 4 + 0] = t.x; hv[q * 4 + 1] = t.y; hv[q * 4 + 2] = t.z; hv[q * 4 + 3] = t.w;
    }
    float* xw2 = (float*)g_xw2;
    #pragma unroll
    for (int r = 0; r < 3; r++) {
        float acc = 0.f;
        #pragma unroll
        for (int k = 0; k < 16; k++) acc += hv[k] * g_W2[r * 128 + k * 8 + c];
        xw2[(r * NN + n) * 8 + c] = acc;
    }
    float acc2 = bias2[c];
    #pragma unroll
    for (int k = 0; k < 16; k++) acc2 += hv[k] * root2[k * 8 + c];
    ((float*)g_rootx2)[gid] = acc2;
}

// Layer-2 edge scatter: 2 threads/edge, each one float4.
__global__ void scatter2(const int* __restrict__ src, const int* __restrict__ dst,
                         const int* __restrict__ et) {
    int gid = blockIdx.x * blockDim.x + threadIdx.x;
    if (gid >= EE * 2) return;
    int e = gid >> 1, half = gid & 1;
    int r = et[e], s = src[e], d = dst[e];
    float4 v = __ldg(&g_xw2[(r * NN + s) * 2 + half]);
    red_add_v4(&g_sums2[(r * NN + d) * 2 + half], v);
}

// Layer-2 finalize + log_softmax. One thread per node.
__global__ void finalize2(float* __restrict__ out) {
    int n = blockIdx.x * blockDim.x + threadIdx.x;
    if (n >= NN) return;
    float v[8];
    {
        float4 a = g_rootx2[n * 2 + 0], b = g_rootx2[n * 2 + 1];
        v[0] = a.x; v[1] = a.y; v[2] = a.z; v[3] = a.w;
        v[4] = b.x; v[5] = b.y; v[6] = b.z; v[7] = b.w;
    }
    const float* cnt = (const float*)g_cnt4;
    #pragma unroll
    for (int r = 0; r < 3; r++) {
        float inv = 1.0f / fmaxf(cnt[r * NN + n], 1.0f);
        float4 s0 = g_sums2[(r * NN + n) * 2 + 0];
        float4 s1 = g_sums2[(r * NN + n) * 2 + 1];
        v[0] += s0.x * inv; v[1] += s0.y * inv; v[2] += s0.z * inv; v[3] += s0.w * inv;
        v[4] += s1.x * inv; v[5] += s1.y * inv; v[6] += s1.z * inv; v[7] += s1.w * inv;
    }
    float m = v[0];
    #pragma unroll
    for (int i = 1; i < 8; i++) m = fmaxf(m, v[i]);
    float s = 0.f;
    #pragma unroll
    for (int i = 0; i < 8; i++) s += expf(v[i] - m);
    float lse = m + logf(s);
    float4 o0 = make_float4(v[0] - lse, v[1] - lse, v[2] - lse, v[3] - lse);
    float4 o1 = make_float4(v[4] - lse, v[5] - lse, v[6] - lse, v[7] - lse);
    float4* o = (float4*)(out + (size_t)n * 8);
    o[0] = o0; o[1] = o1;
}

// ---------------- host ------------------------------------------------------
extern "C" void kernel_launch(void* const* d_in, const int* in_sizes, int n_in,
                              void* d_out, int out_size) {
    // Map inputs by element count (metadata order is unknown; sizes are unique
    // except comp1/comp2 which tie-break by order of appearance).
    const float *x = nullptr, *b1 = nullptr, *c1 = nullptr, *r1 = nullptr, *bs1 = nullptr;
    const float *b2 = nullptr, *c2 = nullptr, *r2 = nullptr, *bs2 = nullptr;
    const int *ei = nullptr, *et = nullptr;
    for (int i = 0; i < n_in; i++) {
        switch (in_sizes[i]) {
            case NN * 3:      x   = (const float*)d_in[i]; break;
            case 2 * EE:      ei  = (const int*)d_in[i];   break;
            case EE:          et  = (const int*)d_in[i];   break;
            case 5 * 3 * 16:  b1  = (const float*)d_in[i]; break;
            case 3 * 16:      r1  = (const float*)d_in[i]; break;
            case 16:          bs1 = (const float*)d_in[i]; break;
            case 5 * 16 * 8:  b2  = (const float*)d_in[i]; break;
            case 16 * 8:      r2  = (const float*)d_in[i]; break;
            case 8:           bs2 = (const float*)d_in[i]; break;
            case 15:          if (!c1) c1 = (const float*)d_in[i];
                              else     c2 = (const float*)d_in[i]; break;
            default: break;
        }
    }
    const int* src = ei;
    const int* dst = ei + EE;
    float* out = (float*)d_out;

    const int T = 256;
    int nzero = 3 * NN * 4 + 3 * NN * 2 + 3 * NN / 4;  // float4 count
    zero_all<<<(nzero + T - 1) / T, T>>>();
    prep_W<<<1, 512>>>(b1, c1, b2, c2);
    dense1<<<(NN * 16 + T - 1) / T, T>>>(x, r1, bs1);
    scatter1<<<(EE * 4) / T, T>>>(src, dst, et);
    finalize1<<<(NN * 16 + T - 1) / T, T>>>();
    dense2<<<(NN * 8 + T - 1) / T, T>>>(r2, bs2);
    scatter2<<<(EE * 2) / T, T>>>(src, dst, et);
    finalize2<<<(NN + T - 1) / T, T>>>(out);
    (void)out_size;
}

// round 2
// speedup vs baseline: 1.4556x; 1.4556x over previous
#include <cuda_runtime.h>
#include <cuda_bf16.h>

#define NN 200000
#define EE 6400000
// R=3, B=5, H=16, C=8

// ---------------- scratch ----------------------------------------------------
__device__ float4 g_x4    [NN];           // (x0, x1, x2, 1.0) per node
__device__ float4 g_sx    [3 * NN];       // per (r,dst): sum x + count in .w
__device__ float4 g_h     [NN * 4];       // layer1 output (post relu), 16 f/node
__device__ float4 g_xw2   [3 * NN * 2];   // [r][n][8] layer2 messages
__device__ float4 g_sums2 [3 * NN * 2];   // per (r,dst) sums, layer2
__device__ float4 g_rootx2[NN * 2];       // h@root2 + bias2
__device__ float  g_W1[3 * 3 * 16];       // comp1 x basis1  [r][i][o]
__device__ float  g_W2[3 * 16 * 8];       // comp2 x basis2  [r][k][c]

// ---------------- vectorized global reduction --------------------------------
__device__ __forceinline__ void red_add_v4(float4* addr, float4 v) {
    asm volatile("red.relaxed.gpu.global.add.v4.f32 [%0], {%1,%2,%3,%4};"
                 :: "l"(addr), "f"(v.x), "f"(v.y), "f"(v.z), "f"(v.w) : "memory");
}

// ---------------- kernels ----------------------------------------------------

// Zero accumulators (graph-replay determinism).
__global__ void zero_all() {
    const int NS1 = 3 * NN;            // sums_x, float4
    const int NS2 = 3 * NN * 2;        // sums2,  float4
    int i = blockIdx.x * blockDim.x + threadIdx.x;
    float4 z = make_float4(0.f, 0.f, 0.f, 0.f);
    if (i < NS1)            g_sx[i] = z;
    else if (i < NS1 + NS2) g_sums2[i - NS1] = z;
}

// Pack x rows into aligned float4 with 1.0 count lane.
__global__ void pack_x(const float* __restrict__ x) {
    int n = blockIdx.x * blockDim.x + threadIdx.x;
    if (n >= NN) return;
    g_x4[n] = make_float4(x[n * 3 + 0], x[n * 3 + 1], x[n * 3 + 2], 1.0f);
}

// W[r] = sum_b comp[r,b] * basis[b]
__global__ void prep_W(const float* __restrict__ b1, const float* __restrict__ c1,
                       const float* __restrict__ b2, const float* __restrict__ c2) {
    int t = threadIdx.x;
    if (t < 144) {  // W1: [r][i][o]
        int r = t / 48, rem = t % 48, i = rem / 16, o = rem % 16;
        float acc = 0.f;
        #pragma unroll
        for (int b = 0; b < 5; b++) acc += c1[r * 5 + b] * b1[(b * 3 + i) * 16 + o];
        g_W1[t] = acc;
    }
    if (t < 384) {  // W2: [r][k][c]
        int r = t / 128, rem = t % 128, k = rem / 8, c = rem % 8;
        float acc = 0.f;
        #pragma unroll
        for (int b = 0; b < 5; b++) acc += c2[r * 5 + b] * b2[(b * 16 + k) * 8 + c];
        g_W2[t] = acc;
    }
}

// Layer-1 edge scatter: 1 thread/edge, ONE red.v4 of (x[src], 1.0).
__global__ void scatter1(const int* __restrict__ src, const int* __restrict__ dst,
                         const int* __restrict__ et) {
    int e = blockIdx.x * blockDim.x + threadIdx.x;
    if (e >= EE) return;
    int r = et[e], s = src[e], d = dst[e];
    float4 v = __ldg(&g_x4[s]);
    red_add_v4(&g_sx[r * NN + d], v);
}

// Layer-1 finalize: h[n] = relu( sum_r (sx_r/cnt_r)·W1[r] + x[n]·root1 + bias1 )
__global__ void finalize1(const float* __restrict__ root1,
                          const float* __restrict__ bias1) {
    int n = blockIdx.x * blockDim.x + threadIdx.x;
    if (n >= NN) return;
    float out[16];
    #pragma unroll
    for (int o = 0; o < 16; o++) out[o] = bias1[o];
    float4 xv = g_x4[n];
    float xi[3] = {xv.x, xv.y, xv.z};
    #pragma unroll
    for (int i = 0; i < 3; i++)
        #pragma unroll
        for (int o = 0; o < 16; o++) out[o] += xi[i] * root1[i * 16 + o];
    #pragma unroll
    for (int r = 0; r < 3; r++) {
        float4 s = g_sx[r * NN + n];
        float inv = 1.0f / fmaxf(s.w, 1.0f);
        float m[3] = {s.x * inv, s.y * inv, s.z * inv};
        #pragma unroll
        for (int i = 0; i < 3; i++)
            #pragma unroll
            for (int o = 0; o < 16; o++) out[o] += m[i] * g_W1[r * 48 + i * 16 + o];
    }
    #pragma unroll
    for (int q = 0; q < 4; q++)
        g_h[n * 4 + q] = make_float4(fmaxf(out[q*4+0], 0.f), fmaxf(out[q*4+1], 0.f),
                                     fmaxf(out[q*4+2], 0.f), fmaxf(out[q*4+3], 0.f));
}

// Layer-2 dense part: xw2[r][n][c] = h[n]·W2[r][:,c]; rootx2 = h@root2 + bias2
__global__ void dense2(const float* __restrict__ root2, const float* __restrict__ bias2) {
    int n = blockIdx.x * blockDim.x + threadIdx.x;
    if (n >= NN) return;
    float hv[16];
    #pragma unroll
    for (int q = 0; q < 4; q++) {
        float4 t = g_h[n * 4 + q];
        hv[q*4+0] = t.x; hv[q*4+1] = t.y; hv[q*4+2] = t.z; hv[q*4+3] = t.w;
    }
    #pragma unroll
    for (int r = 0; r < 3; r++) {
        float acc[8];
        #pragma unroll
        for (int c = 0; c < 8; c++) acc[c] = 0.f;
        #pragma unroll
        for (int k = 0; k < 16; k++)
            #pragma unroll
            for (int c = 0; c < 8; c++) acc[c] += hv[k] * g_W2[r * 128 + k * 8 + c];
        g_xw2[(r * NN + n) * 2 + 0] = make_float4(acc[0], acc[1], acc[2], acc[3]);
        g_xw2[(r * NN + n) * 2 + 1] = make_float4(acc[4], acc[5], acc[6], acc[7]);
    }
    float acc[8];
    #pragma unroll
    for (int c = 0; c < 8; c++) acc[c] = bias2[c];
    #pragma unroll
    for (int k = 0; k < 16; k++)
        #pragma unroll
        for (int c = 0; c < 8; c++) acc[c] += hv[k] * root2[k * 8 + c];
    g_rootx2[n * 2 + 0] = make_float4(acc[0], acc[1], acc[2], acc[3]);
    g_rootx2[n * 2 + 1] = make_float4(acc[4], acc[5], acc[6], acc[7]);
}

// Layer-2 edge scatter: 1 thread/edge, two gathers + two red.v4.
__global__ void scatter2(const int* __restrict__ src, const int* __restrict__ dst,
                         const int* __restrict__ et) {
    int e = blockIdx.x * blockDim.x + threadIdx.x;
    if (e >= EE) return;
    int r = et[e], s = src[e], d = dst[e];
    float4 v0 = __ldg(&g_xw2[(r * NN + s) * 2 + 0]);
    float4 v1 = __ldg(&g_xw2[(r * NN + s) * 2 + 1]);
    red_add_v4(&g_sums2[(r * NN + d) * 2 + 0], v0);
    red_add_v4(&g_sums2[(r * NN + d) * 2 + 1], v1);
}

// Layer-2 finalize + log_softmax. One thread per node. Counts from g_sx.w.
__global__ void finalize2(float* __restrict__ out) {
    int n = blockIdx.x * blockDim.x + threadIdx.x;
    if (n >= NN) return;
    float v[8];
    {
        float4 a = g_rootx2[n * 2 + 0], b = g_rootx2[n * 2 + 1];
        v[0]=a.x; v[1]=a.y; v[2]=a.z; v[3]=a.w;
        v[4]=b.x; v[5]=b.y; v[6]=b.z; v[7]=b.w;
    }
    #pragma unroll
    for (int r = 0; r < 3; r++) {
        float inv = 1.0f / fmaxf(g_sx[r * NN + n].w, 1.0f);
        float4 s0 = g_sums2[(r * NN + n) * 2 + 0];
        float4 s1 = g_sums2[(r * NN + n) * 2 + 1];
        v[0] += s0.x*inv; v[1] += s0.y*inv; v[2] += s0.z*inv; v[3] += s0.w*inv;
        v[4] += s1.x*inv; v[5] += s1.y*inv; v[6] += s1.z*inv; v[7] += s1.w*inv;
    }
    float m = v[0];
    #pragma unroll
    for (int i = 1; i < 8; i++) m = fmaxf(m, v[i]);
    float s = 0.f;
    #pragma unroll
    for (int i = 0; i < 8; i++) s += expf(v[i] - m);
    float lse = m + logf(s);
    float4* o = (float4*)(out + (size_t)n * 8);
    o[0] = make_float4(v[0]-lse, v[1]-lse, v[2]-lse, v[3]-lse);
    o[1] = make_float4(v[4]-lse, v[5]-lse, v[6]-lse, v[7]-lse);
}

// ---------------- host -------------------------------------------------------
extern "C" void kernel_launch(void* const* d_in, const int* in_sizes, int n_in,
                              void* d_out, int out_size) {
    const float *x = nullptr, *b1 = nullptr, *c1 = nullptr, *r1 = nullptr, *bs1 = nullptr;
    const float *b2 = nullptr, *c2 = nullptr, *r2 = nullptr, *bs2 = nullptr;
    const int *ei = nullptr, *et = nullptr;
    for (int i = 0; i < n_in; i++) {
        switch (in_sizes[i]) {
            case NN * 3:      x   = (const float*)d_in[i]; break;
            case 2 * EE:      ei  = (const int*)d_in[i];   break;
            case EE:          et  = (const int*)d_in[i];   break;
            case 5 * 3 * 16:  b1  = (const float*)d_in[i]; break;
            case 3 * 16:      r1  = (const float*)d_in[i]; break;
            case 16:          bs1 = (const float*)d_in[i]; break;
            case 5 * 16 * 8:  b2  = (const float*)d_in[i]; break;
            case 16 * 8:      r2  = (const float*)d_in[i]; break;
            case 8:           bs2 = (const float*)d_in[i]; break;
            case 15:          if (!c1) c1 = (const float*)d_in[i];
                              else     c2 = (const float*)d_in[i]; break;
            default: break;
        }
    }
    const int* src = ei;
    const int* dst = ei + EE;
    float* out = (float*)d_out;

    const int T = 256;
    int nzero = 3 * NN + 3 * NN * 2;   // float4 count
    zero_all<<<(nzero + T - 1) / T, T>>>();
    pack_x<<<(NN + T - 1) / T, T>>>(x);
    prep_W<<<1, 512>>>(b1, c1, b2, c2);
    scatter1<<<(EE + T - 1) / T, T>>>(src, dst, et);
    finalize1<<<(NN + T - 1) / T, T>>>(r1, bs1);
    dense2<<<(NN + T - 1) / T, T>>>(r2, bs2);
    scatter2<<<(EE + T - 1) / T, T>>>(src, dst, et);
    finalize2<<<(NN + T - 1) / T, T>>>(out);
    (void)out_size;
}

// round 4
// speedup vs baseline: 1.5341x; 1.0539x over previous
#include <cuda_runtime.h>
#include <cuda_bf16.h>

#define NN 200000
#define EE 6400000
// R=3, B=5, H=16, C=8

// ---------------- scratch ----------------------------------------------------
__device__ float4 g_x4    [NN];           // (x0, x1, x2, 1.0) per node
__device__ float4 g_sx    [3 * NN];       // per (r,dst): sum x + count in .w
__device__ float4 g_xw2   [3 * NN * 2];   // [r][n][8] layer2 messages
__device__ float4 g_sums2 [3 * NN * 2];   // per (r,dst) sums, layer2
__device__ float4 g_rootx2[NN * 2];       // h@root2 + bias2
__device__ float  g_W1[3 * 3 * 16];       // comp1 x basis1  [r][i][o]
__device__ float  g_W2[3 * 16 * 8];       // comp2 x basis2  [r][k][c]

// ---------------- vectorized global reduction --------------------------------
__device__ __forceinline__ void red_add_v4(float4* addr, float4 v) {
    asm volatile("red.relaxed.gpu.global.add.v4.f32 [%0], {%1,%2,%3,%4};"
                 :: "l"(addr), "f"(v.x), "f"(v.y), "f"(v.z), "f"(v.w) : "memory");
}

// ---------------- kernels ----------------------------------------------------

// Fused prep: pack x, zero g_sx, compute W1/W2 (block 0, stride loops).
__global__ void prep1(const float* __restrict__ x,
                      const float* __restrict__ b1, const float* __restrict__ c1,
                      const float* __restrict__ b2, const float* __restrict__ c2) {
    int n = blockIdx.x * blockDim.x + threadIdx.x;
    if (n < NN) {
        g_x4[n] = make_float4(x[n * 3 + 0], x[n * 3 + 1], x[n * 3 + 2], 1.0f);
        float4 z = make_float4(0.f, 0.f, 0.f, 0.f);
        g_sx[n] = z;
        g_sx[NN + n] = z;
        g_sx[2 * NN + n] = z;
    }
    if (blockIdx.x == 0) {
        for (int t = threadIdx.x; t < 144; t += blockDim.x) {  // W1: [r][i][o]
            int r = t / 48, rem = t % 48, i = rem / 16, o = rem % 16;
            float acc = 0.f;
            #pragma unroll
            for (int b = 0; b < 5; b++) acc += c1[r * 5 + b] * b1[(b * 3 + i) * 16 + o];
            g_W1[t] = acc;
        }
        for (int t = threadIdx.x; t < 384; t += blockDim.x) {  // W2: [r][k][c]
            int r = t / 128, rem = t % 128, k = rem / 8, c = rem % 8;
            float acc = 0.f;
            #pragma unroll
            for (int b = 0; b < 5; b++) acc += c2[r * 5 + b] * b2[(b * 16 + k) * 8 + c];
            g_W2[t] = acc;
        }
    }
}

// Zero the layer-2 accumulator (runs on side stream, overlapped with scatter1).
__global__ void zero2() {
    int i = blockIdx.x * blockDim.x + threadIdx.x;
    if (i < 3 * NN * 2) g_sums2[i] = make_float4(0.f, 0.f, 0.f, 0.f);
}

// Layer-1 edge scatter: 1 thread/edge, ONE red.v4 of (x[src], 1.0).
__global__ void scatter1(const int* __restrict__ src, const int* __restrict__ dst,
                         const int* __restrict__ et) {
    int e = blockIdx.x * blockDim.x + threadIdx.x;
    if (e >= EE) return;
    int r = et[e], s = src[e], d = dst[e];
    float4 v = __ldg(&g_x4[s]);
    red_add_v4(&g_sx[r * NN + d], v);
}

// Fused layer-1 finalize + layer-2 dense (h stays in registers).
__global__ void fin1dense2(const float* __restrict__ root1, const float* __restrict__ bias1,
                           const float* __restrict__ root2, const float* __restrict__ bias2) {
    int n = blockIdx.x * blockDim.x + threadIdx.x;
    if (n >= NN) return;
    float h[16];
    #pragma unroll
    for (int o = 0; o < 16; o++) h[o] = bias1[o];
    float4 xv = g_x4[n];
    float xi[3] = {xv.x, xv.y, xv.z};
    #pragma unroll
    for (int i = 0; i < 3; i++)
        #pragma unroll
        for (int o = 0; o < 16; o++) h[o] += xi[i] * root1[i * 16 + o];
    #pragma unroll
    for (int r = 0; r < 3; r++) {
        float4 s = g_sx[r * NN + n];
        float inv = 1.0f / fmaxf(s.w, 1.0f);
        float m[3] = {s.x * inv, s.y * inv, s.z * inv};
        #pragma unroll
        for (int i = 0; i < 3; i++)
            #pragma unroll
            for (int o = 0; o < 16; o++) h[o] += m[i] * g_W1[r * 48 + i * 16 + o];
    }
    #pragma unroll
    for (int o = 0; o < 16; o++) h[o] = fmaxf(h[o], 0.f);

    #pragma unroll
    for (int r = 0; r < 3; r++) {
        float acc[8];
        #pragma unroll
        for (int c = 0; c < 8; c++) acc[c] = 0.f;
        #pragma unroll
        for (int k = 0; k < 16; k++)
            #pragma unroll
            for (int c = 0; c < 8; c++) acc[c] += h[k] * g_W2[r * 128 + k * 8 + c];
        g_xw2[(r * NN + n) * 2 + 0] = make_float4(acc[0], acc[1], acc[2], acc[3]);
        g_xw2[(r * NN + n) * 2 + 1] = make_float4(acc[4], acc[5], acc[6], acc[7]);
    }
    float acc[8];
    #pragma unroll
    for (int c = 0; c < 8; c++) acc[c] = bias2[c];
    #pragma unroll
    for (int k = 0; k < 16; k++)
        #pragma unroll
        for (int c = 0; c < 8; c++) acc[c] += h[k] * root2[k * 8 + c];
    g_rootx2[n * 2 + 0] = make_float4(acc[0], acc[1], acc[2], acc[3]);
    g_rootx2[n * 2 + 1] = make_float4(acc[4], acc[5], acc[6], acc[7]);
}

// Layer-2 edge scatter: 1 thread/edge, two gathers + two red.v4 (same 32B sector).
__global__ void scatter2(const int* __restrict__ src, const int* __restrict__ dst,
                         const int* __restrict__ et) {
    int e = blockIdx.x * blockDim.x + threadIdx.x;
    if (e >= EE) return;
    int r = et[e], s = src[e], d = dst[e];
    float4 v0 = __ldg(&g_xw2[(r * NN + s) * 2 + 0]);
    float4 v1 = __ldg(&g_xw2[(r * NN + s) * 2 + 1]);
    red_add_v4(&g_sums2[(r * NN + d) * 2 + 0], v0);
    red_add_v4(&g_sums2[(r * NN + d) * 2 + 1], v1);
}

// Layer-2 finalize + log_softmax. One thread per node. Counts from g_sx.w.
__global__ void finalize2(float* __restrict__ out) {
    int n = blockIdx.x * blockDim.x + threadIdx.x;
    if (n >= NN) return;
    float v[8];
    {
        float4 a = g_rootx2[n * 2 + 0], b = g_rootx2[n * 2 + 1];
        v[0]=a.x; v[1]=a.y; v[2]=a.z; v[3]=a.w;
        v[4]=b.x; v[5]=b.y; v[6]=b.z; v[7]=b.w;
    }
    #pragma unroll
    for (int r = 0; r < 3; r++) {
        float inv = 1.0f / fmaxf(g_sx[r * NN + n].w, 1.0f);
        float4 s0 = g_sums2[(r * NN + n) * 2 + 0];
        float4 s1 = g_sums2[(r * NN + n) * 2 + 1];
        v[0] += s0.x*inv; v[1] += s0.y*inv; v[2] += s0.z*inv; v[3] += s0.w*inv;
        v[4] += s1.x*inv; v[5] += s1.y*inv; v[6] += s1.z*inv; v[7] += s1.w*inv;
    }
    float m = v[0];
    #pragma unroll
    for (int i = 1; i < 8; i++) m = fmaxf(m, v[i]);
    float s = 0.f;
    #pragma unroll
    for (int i = 0; i < 8; i++) s += expf(v[i] - m);
    float lse = m + logf(s);
    float4* o = (float4*)(out + (size_t)n * 8);
    o[0] = make_float4(v[0]-lse, v[1]-lse, v[2]-lse, v[3]-lse);
    o[1] = make_float4(v[4]-lse, v[5]-lse, v[6]-lse, v[7]-lse);
}

// ---------------- host -------------------------------------------------------
extern "C" void kernel_launch(void* const* d_in, const int* in_sizes, int n_in,
                              void* d_out, int out_size) {
    const float *x = nullptr, *b1 = nullptr, *c1 = nullptr, *r1 = nullptr, *bs1 = nullptr;
    const float *b2 = nullptr, *c2 = nullptr, *r2 = nullptr, *bs2 = nullptr;
    const int *ei = nullptr, *et = nullptr;
    for (int i = 0; i < n_in; i++) {
        switch (in_sizes[i]) {
            case NN * 3:      x   = (const float*)d_in[i]; break;
            case 2 * EE:      ei  = (const int*)d_in[i];   break;
            case EE:          et  = (const int*)d_in[i];   break;
            case 5 * 3 * 16:  b1  = (const float*)d_in[i]; break;
            case 3 * 16:      r1  = (const float*)d_in[i]; break;
            case 16:          bs1 = (const float*)d_in[i]; break;
            case 5 * 16 * 8:  b2  = (const float*)d_in[i]; break;
            case 16 * 8:      r2  = (const float*)d_in[i]; break;
            case 8:           bs2 = (const float*)d_in[i]; break;
            case 15:          if (!c1) c1 = (const float*)d_in[i];
                              else     c2 = (const float*)d_in[i]; break;
            default: break;
        }
    }
    const int* src = ei;
    const int* dst = ei + EE;
    float* out = (float*)d_out;

    // Lazy resource creation: first call is the (uncaptured) correctness run,
    // so stream/event creation happens outside graph capture.
    static cudaStream_t s_side = nullptr;
    static cudaEvent_t  e_fork = nullptr, e_zero2 = nullptr;
    if (!s_side) {
        cudaStreamCreateWithFlags(&s_side, cudaStreamNonBlocking);
        cudaEventCreateWithFlags(&e_fork,  cudaEventDisableTiming);
        cudaEventCreateWithFlags(&e_zero2, cudaEventDisableTiming);
    }

    const int T = 256;

    // Fork: zero2 (38.4 MB) runs on the side stream, overlapped with prep+scatter1.
    cudaEventRecord(e_fork, 0);
    cudaStreamWaitEvent(s_side, e_fork, 0);
    zero2<<<(3 * NN * 2 + T - 1) / T, T, 0, s_side>>>();
    cudaEventRecord(e_zero2, s_side);

    prep1<<<(NN + T - 1) / T, T>>>(x, b1, c1, b2, c2);
    scatter1<<<EE / T, T>>>(src, dst, et);
    fin1dense2<<<(NN + T - 1) / T, T>>>(r1, bs1, r2, bs2);

    // Join: scatter2 needs g_sums2 zeroed.
    cudaStreamWaitEvent(0, e_zero2, 0);
    scatter2<<<EE / T, T>>>(src, dst, et);
    finalize2<<<(NN + T - 1) / T, T>>>(out);
    (void)out_size;
}

// round 5
// speedup vs baseline: 1.5706x; 1.0238x over previous
#include <cuda_runtime.h>
#include <cuda_bf16.h>

#define NN 200000
#define EE 6400000
// R=3, B=5, H=16, C=8

// ---------------- scratch ----------------------------------------------------
__device__ float4 g_x4    [NN];           // (x0, x1, x2, 1.0) per node
__device__ float4 g_sx    [3 * NN];       // per (r,dst): sum x + count in .w
__device__ float4 g_xw2   [3 * NN * 2];   // [r][n][8] layer2 messages
__device__ float4 g_sums2 [3 * NN * 2];   // per (r,dst) sums, layer2
__device__ float4 g_rootx2[NN * 2];       // h@root2 + bias2
__device__ float  g_W1[3 * 3 * 16];       // comp1 x basis1  [r][i][o]
__device__ float  g_W2[3 * 16 * 8];       // comp2 x basis2  [r][k][c]

// ---------------- constant weights (uniform LDCU path, off the LSU) ----------
__constant__ float c_W1[3 * 3 * 16];
__constant__ float c_W2[3 * 16 * 8];
__constant__ float c_root1[3 * 16];
__constant__ float c_bias1[16];
__constant__ float c_root2[16 * 8];
__constant__ float c_bias2[8];

// ---------------- vectorized global reduction --------------------------------
__device__ __forceinline__ void red_add_v4(float4* addr, float4 v) {
    asm volatile("red.relaxed.gpu.global.add.v4.f32 [%0], {%1,%2,%3,%4};"
                 :: "l"(addr), "f"(v.x), "f"(v.y), "f"(v.z), "f"(v.w) : "memory");
}

// ---------------- kernels ----------------------------------------------------

// Fused prep: pack x, zero g_sx, compute W1/W2 (block 0, stride loops).
__global__ void prep1(const float* __restrict__ x,
                      const float* __restrict__ b1, const float* __restrict__ c1,
                      const float* __restrict__ b2, const float* __restrict__ c2) {
    int n = blockIdx.x * blockDim.x + threadIdx.x;
    if (n < NN) {
        g_x4[n] = make_float4(x[n * 3 + 0], x[n * 3 + 1], x[n * 3 + 2], 1.0f);
        float4 z = make_float4(0.f, 0.f, 0.f, 0.f);
        g_sx[n] = z;
        g_sx[NN + n] = z;
        g_sx[2 * NN + n] = z;
    }
    if (blockIdx.x == 0) {
        for (int t = threadIdx.x; t < 144; t += blockDim.x) {  // W1: [r][i][o]
            int r = t / 48, rem = t % 48, i = rem / 16, o = rem % 16;
            float acc = 0.f;
            #pragma unroll
            for (int b = 0; b < 5; b++) acc += c1[r * 5 + b] * b1[(b * 3 + i) * 16 + o];
            g_W1[t] = acc;
        }
        for (int t = threadIdx.x; t < 384; t += blockDim.x) {  // W2: [r][k][c]
            int r = t / 128, rem = t % 128, k = rem / 8, c = rem % 8;
            float acc = 0.f;
            #pragma unroll
            for (int b = 0; b < 5; b++) acc += c2[r * 5 + b] * b2[(b * 16 + k) * 8 + c];
            g_W2[t] = acc;
        }
    }
}

// Zero the layer-2 accumulator (runs on side stream, overlapped with scatter1).
__global__ void zero2() {
    int i = blockIdx.x * blockDim.x + threadIdx.x;
    if (i < 3 * NN * 2) g_sums2[i] = make_float4(0.f, 0.f, 0.f, 0.f);
}

// Layer-1 edge scatter: 1 thread/edge, ONE red.v4 of (x[src], 1.0).
__global__ void scatter1(const int* __restrict__ src, const int* __restrict__ dst,
                         const int* __restrict__ et) {
    int e = blockIdx.x * blockDim.x + threadIdx.x;
    if (e >= EE) return;
    int r = et[e], s = src[e], d = dst[e];
    float4 v = __ldg(&g_x4[s]);
    red_add_v4(&g_sx[r * NN + d], v);
}

// Fused layer-1 finalize + layer-2 dense (weights from __constant__).
__global__ void fin1dense2() {
    int n = blockIdx.x * blockDim.x + threadIdx.x;
    if (n >= NN) return;
    float h[16];
    #pragma unroll
    for (int o = 0; o < 16; o++) h[o] = c_bias1[o];
    float4 xv = g_x4[n];
    float xi[3] = {xv.x, xv.y, xv.z};
    #pragma unroll
    for (int i = 0; i < 3; i++)
        #pragma unroll
        for (int o = 0; o < 16; o++) h[o] += xi[i] * c_root1[i * 16 + o];
    #pragma unroll
    for (int r = 0; r < 3; r++) {
        float4 s = g_sx[r * NN + n];
        float inv = 1.0f / fmaxf(s.w, 1.0f);
        float m[3] = {s.x * inv, s.y * inv, s.z * inv};
        #pragma unroll
        for (int i = 0; i < 3; i++)
            #pragma unroll
            for (int o = 0; o < 16; o++) h[o] += m[i] * c_W1[r * 48 + i * 16 + o];
    }
    #pragma unroll
    for (int o = 0; o < 16; o++) h[o] = fmaxf(h[o], 0.f);

    #pragma unroll
    for (int r = 0; r < 3; r++) {
        float acc[8];
        #pragma unroll
        for (int c = 0; c < 8; c++) acc[c] = 0.f;
        #pragma unroll
        for (int k = 0; k < 16; k++)
            #pragma unroll
            for (int c = 0; c < 8; c++) acc[c] += h[k] * c_W2[r * 128 + k * 8 + c];
        g_xw2[(r * NN + n) * 2 + 0] = make_float4(acc[0], acc[1], acc[2], acc[3]);
        g_xw2[(r * NN + n) * 2 + 1] = make_float4(acc[4], acc[5], acc[6], acc[7]);
    }
    float acc[8];
    #pragma unroll
    for (int c = 0; c < 8; c++) acc[c] = c_bias2[c];
    #pragma unroll
    for (int k = 0; k < 16; k++)
        #pragma unroll
        for (int c = 0; c < 8; c++) acc[c] += h[k] * c_root2[k * 8 + c];
    g_rootx2[n * 2 + 0] = make_float4(acc[0], acc[1], acc[2], acc[3]);
    g_rootx2[n * 2 + 1] = make_float4(acc[4], acc[5], acc[6], acc[7]);
}

// Layer-2 edge scatter: 1 thread/edge, two gathers + two red.v4 (same 32B sector).
__global__ void scatter2(const int* __restrict__ src, const int* __restrict__ dst,
                         const int* __restrict__ et) {
    int e = blockIdx.x * blockDim.x + threadIdx.x;
    if (e >= EE) return;
    int r = et[e], s = src[e], d = dst[e];
    float4 v0 = __ldg(&g_xw2[(r * NN + s) * 2 + 0]);
    float4 v1 = __ldg(&g_xw2[(r * NN + s) * 2 + 1]);
    red_add_v4(&g_sums2[(r * NN + d) * 2 + 0], v0);
    red_add_v4(&g_sums2[(r * NN + d) * 2 + 1], v1);
}

// Layer-2 finalize + log_softmax. One thread per node. Counts from g_sx.w.
__global__ void finalize2(float* __restrict__ out) {
    int n = blockIdx.x * blockDim.x + threadIdx.x;
    if (n >= NN) return;
    float v[8];
    {
        float4 a = g_rootx2[n * 2 + 0], b = g_rootx2[n * 2 + 1];
        v[0]=a.x; v[1]=a.y; v[2]=a.z; v[3]=a.w;
        v[4]=b.x; v[5]=b.y; v[6]=b.z; v[7]=b.w;
    }
    #pragma unroll
    for (int r = 0; r < 3; r++) {
        float inv = 1.0f / fmaxf(g_sx[r * NN + n].w, 1.0f);
        float4 s0 = g_sums2[(r * NN + n) * 2 + 0];
        float4 s1 = g_sums2[(r * NN + n) * 2 + 1];
        v[0] += s0.x*inv; v[1] += s0.y*inv; v[2] += s0.z*inv; v[3] += s0.w*inv;
        v[4] += s1.x*inv; v[5] += s1.y*inv; v[6] += s1.z*inv; v[7] += s1.w*inv;
    }
    float m = v[0];
    #pragma unroll
    for (int i = 1; i < 8; i++) m = fmaxf(m, v[i]);
    float s = 0.f;
    #pragma unroll
    for (int i = 0; i < 8; i++) s += expf(v[i] - m);
    float lse = m + logf(s);
    float4* o = (float4*)(out + (size_t)n * 8);
    o[0] = make_float4(v[0]-lse, v[1]-lse, v[2]-lse, v[3]-lse);
    o[1] = make_float4(v[4]-lse, v[5]-lse, v[6]-lse, v[7]-lse);
}

// ---------------- host -------------------------------------------------------
extern "C" void kernel_launch(void* const* d_in, const int* in_sizes, int n_in,
                              void* d_out, int out_size) {
    const float *x = nullptr, *b1 = nullptr, *c1 = nullptr, *r1 = nullptr, *bs1 = nullptr;
    const float *b2 = nullptr, *c2 = nullptr, *r2 = nullptr, *bs2 = nullptr;
    const int *ei = nullptr, *et = nullptr;
    for (int i = 0; i < n_in; i++) {
        switch (in_sizes[i]) {
            case NN * 3:      x   = (const float*)d_in[i]; break;
            case 2 * EE:      ei  = (const int*)d_in[i];   break;
            case EE:          et  = (const int*)d_in[i];   break;
            case 5 * 3 * 16:  b1  = (const float*)d_in[i]; break;
            case 3 * 16:      r1  = (const float*)d_in[i]; break;
            case 16:          bs1 = (const float*)d_in[i]; break;
            case 5 * 16 * 8:  b2  = (const float*)d_in[i]; break;
            case 16 * 8:      r2  = (const float*)d_in[i]; break;
            case 8:           bs2 = (const float*)d_in[i]; break;
            case 15:          if (!c1) c1 = (const float*)d_in[i];
                              else     c2 = (const float*)d_in[i]; break;
            default: break;
        }
    }
    const int* src = ei;
    const int* dst = ei + EE;
    float* out = (float*)d_out;

    // Lazy resource creation: first call is the (uncaptured) correctness run,
    // so stream/event creation and symbol-address lookup happen outside capture.
    static cudaStream_t s_side = nullptr;
    static cudaEvent_t  e_fork = nullptr, e_zero2 = nullptr;
    static void *a_W1 = nullptr, *a_W2 = nullptr;
    if (!s_side) {
        cudaStreamCreateWithFlags(&s_side, cudaStreamNonBlocking);
        cudaEventCreateWithFlags(&e_fork,  cudaEventDisableTiming);
        cudaEventCreateWithFlags(&e_zero2, cudaEventDisableTiming);
        cudaGetSymbolAddress(&a_W1, g_W1);
        cudaGetSymbolAddress(&a_W2, g_W2);
    }

    const int T = 256;

    // Fork: zero2 (38.4 MB) runs on the side stream, overlapped with prep+scatter1.
    cudaEventRecord(e_fork, 0);
    cudaStreamWaitEvent(s_side, e_fork, 0);
    zero2<<<(3 * NN * 2 + T - 1) / T, T, 0, s_side>>>();
    cudaEventRecord(e_zero2, s_side);

    // Root/bias weights straight into constant memory (D2D memcpy nodes).
    cudaMemcpyToSymbolAsync(c_root1, r1, 48 * sizeof(float),  0, cudaMemcpyDeviceToDevice, 0);
    cudaMemcpyToSymbolAsync(c_bias1, bs1, 16 * sizeof(float), 0, cudaMemcpyDeviceToDevice, 0);
    cudaMemcpyToSymbolAsync(c_root2, r2, 128 * sizeof(float), 0, cudaMemcpyDeviceToDevice, 0);
    cudaMemcpyToSymbolAsync(c_bias2, bs2, 8 * sizeof(float),  0, cudaMemcpyDeviceToDevice, 0);

    prep1<<<(NN + T - 1) / T, T>>>(x, b1, c1, b2, c2);

    // Basis-combined W into constant memory (after prep1 computes them).
    cudaMemcpyToSymbolAsync(c_W1, a_W1, 144 * sizeof(float), 0, cudaMemcpyDeviceToDevice, 0);
    cudaMemcpyToSymbolAsync(c_W2, a_W2, 384 * sizeof(float), 0, cudaMemcpyDeviceToDevice, 0);

    scatter1<<<EE / T, T>>>(src, dst, et);
    fin1dense2<<<(NN + T - 1) / T, T>>>();

    // Join: scatter2 needs g_sums2 zeroed.
    cudaStreamWaitEvent(0, e_zero2, 0);
    scatter2<<<EE / T, T>>>(src, dst, et);
    finalize2<<<(NN + T - 1) / T, T>>>(out);
    (void)out_size;
}

// round 6
// speedup vs baseline: 1.6364x; 1.0419x over previous
#include <cuda_runtime.h>
#include <cuda_bf16.h>

#define NN 200000
#define EE 6400000
// R=3, B=5, H=16, C=8

// ---------------- scratch ----------------------------------------------------
__device__ float4 g_x4    [NN];           // (x0, x1, x2, 1.0) per node
__device__ float4 g_sx    [3 * NN];       // per (r,dst): sum x + count in .w
__device__ float4 g_xw2   [3 * NN * 2];   // [r][n][8] layer2 messages
__device__ float4 g_sums2 [3 * NN * 2];   // per (r,dst) sums, layer2
__device__ float4 g_rootx2[NN * 2];       // h@root2 + bias2
__device__ float  g_cpack [728];          // staging for all weights

// ---------------- constant weights (one packed bank, one memcpy) -------------
// Layout: W1[144] | W2[384] | root1[48] | bias1[16] | root2[128] | bias2[8]
__constant__ float c_pack[728];
#define CW1(i) c_pack[(i)]
#define CW2(i) c_pack[144 + (i)]
#define CR1(i) c_pack[528 + (i)]
#define CB1(i) c_pack[576 + (i)]
#define CR2(i) c_pack[592 + (i)]
#define CB2(i) c_pack[720 + (i)]

// ---------------- vectorized global reduction --------------------------------
__device__ __forceinline__ void red_add_v4(float4* addr, float4 v) {
    asm volatile("red.relaxed.gpu.global.add.v4.f32 [%0], {%1,%2,%3,%4};"
                 :: "l"(addr), "f"(v.x), "f"(v.y), "f"(v.z), "f"(v.w) : "memory");
}

// ---------------- kernels ----------------------------------------------------

// Fused prep: pack x, zero g_sx, build the full weight pack (block 0).
__global__ void prep1(const float* __restrict__ x,
                      const float* __restrict__ b1, const float* __restrict__ c1,
                      const float* __restrict__ b2, const float* __restrict__ c2,
                      const float* __restrict__ r1, const float* __restrict__ bs1,
                      const float* __restrict__ r2, const float* __restrict__ bs2) {
    int n = blockIdx.x * blockDim.x + threadIdx.x;
    if (n < NN) {
        g_x4[n] = make_float4(x[n * 3 + 0], x[n * 3 + 1], x[n * 3 + 2], 1.0f);
        float4 z = make_float4(0.f, 0.f, 0.f, 0.f);
        g_sx[n] = z;
        g_sx[NN + n] = z;
        g_sx[2 * NN + n] = z;
    }
    if (blockIdx.x == 0) {
        for (int t = threadIdx.x; t < 144; t += blockDim.x) {  // W1: [r][i][o]
            int r = t / 48, rem = t % 48, i = rem / 16, o = rem % 16;
            float acc = 0.f;
            #pragma unroll
            for (int b = 0; b < 5; b++) acc += c1[r * 5 + b] * b1[(b * 3 + i) * 16 + o];
            g_cpack[t] = acc;
        }
        for (int t = threadIdx.x; t < 384; t += blockDim.x) {  // W2: [r][k][c]
            int r = t / 128, rem = t % 128, k = rem / 8, c = rem % 8;
            float acc = 0.f;
            #pragma unroll
            for (int b = 0; b < 5; b++) acc += c2[r * 5 + b] * b2[(b * 16 + k) * 8 + c];
            g_cpack[144 + t] = acc;
        }
        for (int t = threadIdx.x; t < 48; t += blockDim.x)  g_cpack[528 + t] = r1[t];
        for (int t = threadIdx.x; t < 16; t += blockDim.x)  g_cpack[576 + t] = bs1[t];
        for (int t = threadIdx.x; t < 128; t += blockDim.x) g_cpack[592 + t] = r2[t];
        for (int t = threadIdx.x; t < 8; t += blockDim.x)   g_cpack[720 + t] = bs2[t];
    }
}

// Layer-1 edge scatter: 1 thread/edge, ONE red.v4 of (x[src], 1.0).
__global__ void scatter1(const int* __restrict__ src, const int* __restrict__ dst,
                         const int* __restrict__ et) {
    int e = blockIdx.x * blockDim.x + threadIdx.x;
    if (e >= EE) return;
    int r = et[e], s = src[e], d = dst[e];
    float4 v = __ldg(&g_x4[s]);
    red_add_v4(&g_sx[r * NN + d], v);
}

// Fused: layer-1 finalize + layer-2 dense + zero g_sums2 (L2-idle window).
__global__ void fin1dense2() {
    int n = blockIdx.x * blockDim.x + threadIdx.x;
    if (n >= NN) return;
    float h[16];
    #pragma unroll
    for (int o = 0; o < 16; o++) h[o] = CB1(o);
    float4 xv = g_x4[n];
    float xi[3] = {xv.x, xv.y, xv.z};
    #pragma unroll
    for (int i = 0; i < 3; i++)
        #pragma unroll
        for (int o = 0; o < 16; o++) h[o] += xi[i] * CR1(i * 16 + o);
    #pragma unroll
    for (int r = 0; r < 3; r++) {
        float4 s = g_sx[r * NN + n];
        float inv = 1.0f / fmaxf(s.w, 1.0f);
        float m[3] = {s.x * inv, s.y * inv, s.z * inv};
        #pragma unroll
        for (int i = 0; i < 3; i++)
            #pragma unroll
            for (int o = 0; o < 16; o++) h[o] += m[i] * CW1(r * 48 + i * 16 + o);
    }
    #pragma unroll
    for (int o = 0; o < 16; o++) h[o] = fmaxf(h[o], 0.f);

    float4 z = make_float4(0.f, 0.f, 0.f, 0.f);
    #pragma unroll
    for (int r = 0; r < 3; r++) {
        float acc[8];
        #pragma unroll
        for (int c = 0; c < 8; c++) acc[c] = 0.f;
        #pragma unroll
        for (int k = 0; k < 16; k++)
            #pragma unroll
            for (int c = 0; c < 8; c++) acc[c] += h[k] * CW2(r * 128 + k * 8 + c);
        g_xw2[(r * NN + n) * 2 + 0] = make_float4(acc[0], acc[1], acc[2], acc[3]);
        g_xw2[(r * NN + n) * 2 + 1] = make_float4(acc[4], acc[5], acc[6], acc[7]);
        g_sums2[(r * NN + n) * 2 + 0] = z;     // zero accumulator inline
        g_sums2[(r * NN + n) * 2 + 1] = z;
    }
    float acc[8];
    #pragma unroll
    for (int c = 0; c < 8; c++) acc[c] = CB2(c);
    #pragma unroll
    for (int k = 0; k < 16; k++)
        #pragma unroll
        for (int c = 0; c < 8; c++) acc[c] += h[k] * CR2(k * 8 + c);
    g_rootx2[n * 2 + 0] = make_float4(acc[0], acc[1], acc[2], acc[3]);
    g_rootx2[n * 2 + 1] = make_float4(acc[4], acc[5], acc[6], acc[7]);
}

// Layer-2 edge scatter: 1 thread/edge, two gathers + two red.v4 (same 32B sector).
__global__ void scatter2(const int* __restrict__ src, const int* __restrict__ dst,
                         const int* __restrict__ et) {
    int e = blockIdx.x * blockDim.x + threadIdx.x;
    if (e >= EE) return;
    int r = et[e], s = src[e], d = dst[e];
    float4 v0 = __ldg(&g_xw2[(r * NN + s) * 2 + 0]);
    float4 v1 = __ldg(&g_xw2[(r * NN + s) * 2 + 1]);
    red_add_v4(&g_sums2[(r * NN + d) * 2 + 0], v0);
    red_add_v4(&g_sums2[(r * NN + d) * 2 + 1], v1);
}

// Layer-2 finalize + log_softmax. One thread per node. Counts from g_sx.w.
__global__ void finalize2(float* __restrict__ out) {
    int n = blockIdx.x * blockDim.x + threadIdx.x;
    if (n >= NN) return;
    float v[8];
    {
        float4 a = g_rootx2[n * 2 + 0], b = g_rootx2[n * 2 + 1];
        v[0]=a.x; v[1]=a.y; v[2]=a.z; v[3]=a.w;
        v[4]=b.x; v[5]=b.y; v[6]=b.z; v[7]=b.w;
    }
    #pragma unroll
    for (int r = 0; r < 3; r++) {
        float inv = 1.0f / fmaxf(g_sx[r * NN + n].w, 1.0f);
        float4 s0 = g_sums2[(r * NN + n) * 2 + 0];
        float4 s1 = g_sums2[(r * NN + n) * 2 + 1];
        v[0] += s0.x*inv; v[1] += s0.y*inv; v[2] += s0.z*inv; v[3] += s0.w*inv;
        v[4] += s1.x*inv; v[5] += s1.y*inv; v[6] += s1.z*inv; v[7] += s1.w*inv;
    }
    float m = v[0];
    #pragma unroll
    for (int i = 1; i < 8; i++) m = fmaxf(m, v[i]);
    float s = 0.f;
    #pragma unroll
    for (int i = 0; i < 8; i++) s += expf(v[i] - m);
    float lse = m + logf(s);
    float4* o = (float4*)(out + (size_t)n * 8);
    o[0] = make_float4(v[0]-lse, v[1]-lse, v[2]-lse, v[3]-lse);
    o[1] = make_float4(v[4]-lse, v[5]-lse, v[6]-lse, v[7]-lse);
}

// ---------------- host -------------------------------------------------------
extern "C" void kernel_launch(void* const* d_in, const int* in_sizes, int n_in,
                              void* d_out, int out_size) {
    const float *x = nullptr, *b1 = nullptr, *c1 = nullptr, *r1 = nullptr, *bs1 = nullptr;
    const float *b2 = nullptr, *c2 = nullptr, *r2 = nullptr, *bs2 = nullptr;
    const int *ei = nullptr, *et = nullptr;
    for (int i = 0; i < n_in; i++) {
        switch (in_sizes[i]) {
            case NN * 3:      x   = (const float*)d_in[i]; break;
            case 2 * EE:      ei  = (const int*)d_in[i];   break;
            case EE:          et  = (const int*)d_in[i];   break;
            case 5 * 3 * 16:  b1  = (const float*)d_in[i]; break;
            case 3 * 16:      r1  = (const float*)d_in[i]; break;
            case 16:          bs1 = (const float*)d_in[i]; break;
            case 5 * 16 * 8:  b2  = (const float*)d_in[i]; break;
            case 16 * 8:      r2  = (const float*)d_in[i]; break;
            case 8:           bs2 = (const float*)d_in[i]; break;
            case 15:          if (!c1) c1 = (const float*)d_in[i];
                              else     c2 = (const float*)d_in[i]; break;
            default: break;
        }
    }
    const int* src = ei;
    const int* dst = ei + EE;
    float* out = (float*)d_out;

    // Lazy resource creation (first call is uncaptured correctness run).
    static cudaStream_t s_side = nullptr;
    static cudaEvent_t  e_prep = nullptr, e_cpy = nullptr;
    static void* a_cpack = nullptr;
    if (!s_side) {
        cudaStreamCreateWithFlags(&s_side, cudaStreamNonBlocking);
        cudaEventCreateWithFlags(&e_prep, cudaEventDisableTiming);
        cudaEventCreateWithFlags(&e_cpy,  cudaEventDisableTiming);
        cudaGetSymbolAddress(&a_cpack, g_cpack);
    }

    const int T = 256;

    prep1<<<(NN + T - 1) / T, T>>>(x, b1, c1, b2, c2, r1, bs1, r2, bs2);

    // Single weight memcpy on side stream — hidden behind scatter1.
    cudaEventRecord(e_prep, 0);
    cudaStreamWaitEvent(s_side, e_prep, 0);
    cudaMemcpyToSymbolAsync(c_pack, a_cpack, 728 * sizeof(float), 0,
                            cudaMemcpyDeviceToDevice, s_side);
    cudaEventRecord(e_cpy, s_side);

    scatter1<<<EE / T, T>>>(src, dst, et);

    cudaStreamWaitEvent(0, e_cpy, 0);
    fin1dense2<<<(NN + T - 1) / T, T>>>();
    scatter2<<<EE / T, T>>>(src, dst, et);
    finalize2<<<(NN + T - 1) / T, T>>>(out);
    (void)out_size;
}

// round 7
// speedup vs baseline: 1.7003x; 1.0390x over previous
#include <cuda_runtime.h>
#include <cuda_fp16.h>
#include <cuda_bf16.h>

#define NN 200000
#define EE 6400000
// R=3, B=5, H=16, C=8

// ---------------- scratch ----------------------------------------------------
__device__ float4 g_x4    [NN];           // (x0, x1, x2, 1.0) per node
__device__ float4 g_sx    [3 * NN];       // per (r,dst): sum x + count in .w
__device__ uint4  g_xw2h  [3 * NN];       // [r][n][8] layer2 messages, fp16 (16B)
__device__ float4 g_sums2 [3 * NN * 2];   // per (r,dst) sums, layer2 (f32)
__device__ float4 g_rootx2[NN * 2];       // h@root2 + bias2
__device__ float  g_cpack [728];          // staging for all weights

// ---------------- constant weights (one packed bank, one memcpy) -------------
// Layout: W1[144] | W2[384] | root1[48] | bias1[16] | root2[128] | bias2[8]
__constant__ float c_pack[728];
#define CW1(i) c_pack[(i)]
#define CW2(i) c_pack[144 + (i)]
#define CR1(i) c_pack[528 + (i)]
#define CB1(i) c_pack[576 + (i)]
#define CR2(i) c_pack[592 + (i)]
#define CB2(i) c_pack[720 + (i)]

// ---------------- vectorized global reduction --------------------------------
__device__ __forceinline__ void red_add_v4(float4* addr, float4 v) {
    asm volatile("red.relaxed.gpu.global.add.v4.f32 [%0], {%1,%2,%3,%4};"
                 :: "l"(addr), "f"(v.x), "f"(v.y), "f"(v.z), "f"(v.w) : "memory");
}

// ---------------- kernels ----------------------------------------------------

// Fused prep: pack x, zero g_sx, build the full weight pack (block 0).
__global__ void prep1(const float* __restrict__ x,
                      const float* __restrict__ b1, const float* __restrict__ c1,
                      const float* __restrict__ b2, const float* __restrict__ c2,
                      const float* __restrict__ r1, const float* __restrict__ bs1,
                      const float* __restrict__ r2, const float* __restrict__ bs2) {
    int n = blockIdx.x * blockDim.x + threadIdx.x;
    if (n < NN) {
        g_x4[n] = make_float4(x[n * 3 + 0], x[n * 3 + 1], x[n * 3 + 2], 1.0f);
        float4 z = make_float4(0.f, 0.f, 0.f, 0.f);
        g_sx[n] = z;
        g_sx[NN + n] = z;
        g_sx[2 * NN + n] = z;
    }
    if (blockIdx.x == 0) {
        for (int t = threadIdx.x; t < 144; t += blockDim.x) {  // W1: [r][i][o]
            int r = t / 48, rem = t % 48, i = rem / 16, o = rem % 16;
            float acc = 0.f;
            #pragma unroll
            for (int b = 0; b < 5; b++) acc += c1[r * 5 + b] * b1[(b * 3 + i) * 16 + o];
            g_cpack[t] = acc;
        }
        for (int t = threadIdx.x; t < 384; t += blockDim.x) {  // W2: [r][k][c]
            int r = t / 128, rem = t % 128, k = rem / 8, c = rem % 8;
            float acc = 0.f;
            #pragma unroll
            for (int b = 0; b < 5; b++) acc += c2[r * 5 + b] * b2[(b * 16 + k) * 8 + c];
            g_cpack[144 + t] = acc;
        }
        for (int t = threadIdx.x; t < 48; t += blockDim.x)  g_cpack[528 + t] = r1[t];
        for (int t = threadIdx.x; t < 16; t += blockDim.x)  g_cpack[576 + t] = bs1[t];
        for (int t = threadIdx.x; t < 128; t += blockDim.x) g_cpack[592 + t] = r2[t];
        for (int t = threadIdx.x; t < 8; t += blockDim.x)   g_cpack[720 + t] = bs2[t];
    }
}

// Layer-1 edge scatter: 1 thread/edge, ONE red.v4 of (x[src], 1.0).
__global__ void scatter1(const int* __restrict__ src, const int* __restrict__ dst,
                         const int* __restrict__ et) {
    int e = blockIdx.x * blockDim.x + threadIdx.x;
    if (e >= EE) return;
    int r = et[e], s = src[e], d = dst[e];
    float4 v = __ldg(&g_x4[s]);
    red_add_v4(&g_sx[r * NN + d], v);
}

// Fused: layer-1 finalize + layer-2 dense (fp16 messages) + zero g_sums2.
__global__ void fin1dense2() {
    int n = blockIdx.x * blockDim.x + threadIdx.x;
    if (n >= NN) return;
    float h[16];
    #pragma unroll
    for (int o = 0; o < 16; o++) h[o] = CB1(o);
    float4 xv = g_x4[n];
    float xi[3] = {xv.x, xv.y, xv.z};
    #pragma unroll
    for (int i = 0; i < 3; i++)
        #pragma unroll
        for (int o = 0; o < 16; o++) h[o] += xi[i] * CR1(i * 16 + o);
    #pragma unroll
    for (int r = 0; r < 3; r++) {
        float4 s = g_sx[r * NN + n];
        float inv = 1.0f / fmaxf(s.w, 1.0f);
        float m[3] = {s.x * inv, s.y * inv, s.z * inv};
        #pragma unroll
        for (int i = 0; i < 3; i++)
            #pragma unroll
            for (int o = 0; o < 16; o++) h[o] += m[i] * CW1(r * 48 + i * 16 + o);
    }
    #pragma unroll
    for (int o = 0; o < 16; o++) h[o] = fmaxf(h[o], 0.f);

    float4 z = make_float4(0.f, 0.f, 0.f, 0.f);
    #pragma unroll
    for (int r = 0; r < 3; r++) {
        float acc[8];
        #pragma unroll
        for (int c = 0; c < 8; c++) acc[c] = 0.f;
        #pragma unroll
        for (int k = 0; k < 16; k++)
            #pragma unroll
            for (int c = 0; c < 8; c++) acc[c] += h[k] * CW2(r * 128 + k * 8 + c);
        // Pack 8 f32 -> 8 fp16 (one 16B store).
        __half2 p0 = __float22half2_rn(make_float2(acc[0], acc[1]));
        __half2 p1 = __float22half2_rn(make_float2(acc[2], acc[3]));
        __half2 p2 = __float22half2_rn(make_float2(acc[4], acc[5]));
        __half2 p3 = __float22half2_rn(make_float2(acc[6], acc[7]));
        uint4 packed;
        packed.x = *reinterpret_cast<unsigned*>(&p0);
        packed.y = *reinterpret_cast<unsigned*>(&p1);
        packed.z = *reinterpret_cast<unsigned*>(&p2);
        packed.w = *reinterpret_cast<unsigned*>(&p3);
        g_xw2h[r * NN + n] = packed;
        g_sums2[(r * NN + n) * 2 + 0] = z;     // zero accumulator inline
        g_sums2[(r * NN + n) * 2 + 1] = z;
    }
    float acc[8];
    #pragma unroll
    for (int c = 0; c < 8; c++) acc[c] = CB2(c);
    #pragma unroll
    for (int k = 0; k < 16; k++)
        #pragma unroll
        for (int c = 0; c < 8; c++) acc[c] += h[k] * CR2(k * 8 + c);
    g_rootx2[n * 2 + 0] = make_float4(acc[0], acc[1], acc[2], acc[3]);
    g_rootx2[n * 2 + 1] = make_float4(acc[4], acc[5], acc[6], acc[7]);
}

// Layer-2 edge scatter: 1 thread/edge, ONE 16B fp16 gather + two f32 red.v4.
__global__ void scatter2(const int* __restrict__ src, const int* __restrict__ dst,
                         const int* __restrict__ et) {
    int e = blockIdx.x * blockDim.x + threadIdx.x;
    if (e >= EE) return;
    int r = et[e], s = src[e], d = dst[e];
    uint4 p = __ldg(&g_xw2h[r * NN + s]);
    float2 f0 = __half22float2(*reinterpret_cast<__half2*>(&p.x));
    float2 f1 = __half22float2(*reinterpret_cast<__half2*>(&p.y));
    float2 f2 = __half22float2(*reinterpret_cast<__half2*>(&p.z));
    float2 f3 = __half22float2(*reinterpret_cast<__half2*>(&p.w));
    red_add_v4(&g_sums2[(r * NN + d) * 2 + 0], make_float4(f0.x, f0.y, f1.x, f1.y));
    red_add_v4(&g_sums2[(r * NN + d) * 2 + 1], make_float4(f2.x, f2.y, f3.x, f3.y));
}

// Layer-2 finalize + log_softmax. One thread per node. Counts from g_sx.w.
__global__ void finalize2(float* __restrict__ out) {
    int n = blockIdx.x * blockDim.x + threadIdx.x;
    if (n >= NN) return;
    float v[8];
    {
        float4 a = g_rootx2[n * 2 + 0], b = g_rootx2[n * 2 + 1];
        v[0]=a.x; v[1]=a.y; v[2]=a.z; v[3]=a.w;
        v[4]=b.x; v[5]=b.y; v[6]=b.z; v[7]=b.w;
    }
    #pragma unroll
    for (int r = 0; r < 3; r++) {
        float inv = 1.0f / fmaxf(g_sx[r * NN + n].w, 1.0f);
        float4 s0 = g_sums2[(r * NN + n) * 2 + 0];
        float4 s1 = g_sums2[(r * NN + n) * 2 + 1];
        v[0] += s0.x*inv; v[1] += s0.y*inv; v[2] += s0.z*inv; v[3] += s0.w*inv;
        v[4] += s1.x*inv; v[5] += s1.y*inv; v[6] += s1.z*inv; v[7] += s1.w*inv;
    }
    float m = v[0];
    #pragma unroll
    for (int i = 1; i < 8; i++) m = fmaxf(m, v[i]);
    float s = 0.f;
    #pragma unroll
    for (int i = 0; i < 8; i++) s += expf(v[i] - m);
    float lse = m + logf(s);
    float4* o = (float4*)(out + (size_t)n * 8);
    o[0] = make_float4(v[0]-lse, v[1]-lse, v[2]-lse, v[3]-lse);
    o[1] = make_float4(v[4]-lse, v[5]-lse, v[6]-lse, v[7]-lse);
}

// ---------------- host -------------------------------------------------------
extern "C" void kernel_launch(void* const* d_in, const int* in_sizes, int n_in,
                              void* d_out, int out_size) {
    const float *x = nullptr, *b1 = nullptr, *c1 = nullptr, *r1 = nullptr, *bs1 = nullptr;
    const float *b2 = nullptr, *c2 = nullptr, *r2 = nullptr, *bs2 = nullptr;
    const int *ei = nullptr, *et = nullptr;
    for (int i = 0; i < n_in; i++) {
        switch (in_sizes[i]) {
            case NN * 3:      x   = (const float*)d_in[i]; break;
            case 2 * EE:      ei  = (const int*)d_in[i];   break;
            case EE:          et  = (const int*)d_in[i];   break;
            case 5 * 3 * 16:  b1  = (const float*)d_in[i]; break;
            case 3 * 16:      r1  = (const float*)d_in[i]; break;
            case 16:          bs1 = (const float*)d_in[i]; break;
            case 5 * 16 * 8:  b2  = (const float*)d_in[i]; break;
            case 16 * 8:      r2  = (const float*)d_in[i]; break;
            case 8:           bs2 = (const float*)d_in[i]; break;
            case 15:          if (!c1) c1 = (const float*)d_in[i];
                              else     c2 = (const float*)d_in[i]; break;
            default: break;
        }
    }
    const int* src = ei;
    const int* dst = ei + EE;
    float* out = (float*)d_out;

    // Lazy resource creation (first call is uncaptured correctness run).
    static cudaStream_t s_side = nullptr;
    static cudaEvent_t  e_prep = nullptr, e_cpy = nullptr;
    static void* a_cpack = nullptr;
    if (!s_side) {
        cudaStreamCreateWithFlags(&s_side, cudaStreamNonBlocking);
        cudaEventCreateWithFlags(&e_prep, cudaEventDisableTiming);
        cudaEventCreateWithFlags(&e_cpy,  cudaEventDisableTiming);
        cudaGetSymbolAddress(&a_cpack, g_cpack);
    }

    const int T = 256;

    prep1<<<(NN + T - 1) / T, T>>>(x, b1, c1, b2, c2, r1, bs1, r2, bs2);

    // Single weight memcpy on side stream — hidden behind scatter1.
    cudaEventRecord(e_prep, 0);
    cudaStreamWaitEvent(s_side, e_prep, 0);
    cudaMemcpyToSymbolAsync(c_pack, a_cpack, 728 * sizeof(float), 0,
                            cudaMemcpyDeviceToDevice, s_side);
    cudaEventRecord(e_cpy, s_side);

    scatter1<<<EE / T, T>>>(src, dst, et);

    cudaStreamWaitEvent(0, e_cpy, 0);
    fin1dense2<<<(NN + T - 1) / T, T>>>();
    scatter2<<<EE / T, T>>>(src, dst, et);
    finalize2<<<(NN + T - 1) / T, T>>>(out);
    (void)out_size;
}

// round 8
// speedup vs baseline: 2.0860x; 1.2268x over previous
#include <cuda_runtime.h>
#include <cuda_fp16.h>
#include <cuda_bf16.h>

#define NN 200000
#define EE 6400000
// R=3, B=5, H=16, C=8

// ---------------- scratch ----------------------------------------------------
__device__ float4 g_x4    [NN];           // (x0, x1, x2, 1.0) per node
__device__ float4 g_sx    [3 * NN];       // per (r,dst): sum x + count in .w
__device__ uint4  g_xw2h  [3 * NN];       // [r][n][8] layer2 messages, fp16 (16B)
__device__ uint4  g_sums2h[3 * NN];       // per (r,dst) sums, layer2, fp16 (16B)
__device__ float4 g_rootx2[NN * 2];       // h@root2 + bias2
__device__ float  g_cpack [728];          // staging for all weights

// ---------------- constant weights (one packed bank, one memcpy) -------------
// Layout: W1[144] | W2[384] | root1[48] | bias1[16] | root2[128] | bias2[8]
__constant__ float c_pack[728];
#define CW1(i) c_pack[(i)]
#define CW2(i) c_pack[144 + (i)]
#define CR1(i) c_pack[528 + (i)]
#define CB1(i) c_pack[576 + (i)]
#define CR2(i) c_pack[592 + (i)]
#define CB2(i) c_pack[720 + (i)]

// ---------------- vectorized global reductions -------------------------------
__device__ __forceinline__ void red_add_v4(float4* addr, float4 v) {
    asm volatile("red.relaxed.gpu.global.add.v4.f32 [%0], {%1,%2,%3,%4};"
                 :: "l"(addr), "f"(v.x), "f"(v.y), "f"(v.z), "f"(v.w) : "memory");
}
// 8 half adds in one 16B reduction (sm_90+ vector half atomics).
__device__ __forceinline__ void red_add_v4h2(uint4* addr, uint4 v) {
    asm volatile("red.relaxed.gpu.global.add.noftz.v4.f16x2 [%0], {%1,%2,%3,%4};"
                 :: "l"(addr), "r"(v.x), "r"(v.y), "r"(v.z), "r"(v.w) : "memory");
}

// ---------------- kernels ----------------------------------------------------

// Fused prep: pack x, zero g_sx, build the full weight pack (block 0).
__global__ void prep1(const float* __restrict__ x,
                      const float* __restrict__ b1, const float* __restrict__ c1,
                      const float* __restrict__ b2, const float* __restrict__ c2,
                      const float* __restrict__ r1, const float* __restrict__ bs1,
                      const float* __restrict__ r2, const float* __restrict__ bs2) {
    int n = blockIdx.x * blockDim.x + threadIdx.x;
    if (n < NN) {
        g_x4[n] = make_float4(x[n * 3 + 0], x[n * 3 + 1], x[n * 3 + 2], 1.0f);
        float4 z = make_float4(0.f, 0.f, 0.f, 0.f);
        g_sx[n] = z;
        g_sx[NN + n] = z;
        g_sx[2 * NN + n] = z;
    }
    if (blockIdx.x == 0) {
        for (int t = threadIdx.x; t < 144; t += blockDim.x) {  // W1: [r][i][o]
            int r = t / 48, rem = t % 48, i = rem / 16, o = rem % 16;
            float acc = 0.f;
            #pragma unroll
            for (int b = 0; b < 5; b++) acc += c1[r * 5 + b] * b1[(b * 3 + i) * 16 + o];
            g_cpack[t] = acc;
        }
        for (int t = threadIdx.x; t < 384; t += blockDim.x) {  // W2: [r][k][c]
            int r = t / 128, rem = t % 128, k = rem / 8, c = rem % 8;
            float acc = 0.f;
            #pragma unroll
            for (int b = 0; b < 5; b++) acc += c2[r * 5 + b] * b2[(b * 16 + k) * 8 + c];
            g_cpack[144 + t] = acc;
        }
        for (int t = threadIdx.x; t < 48; t += blockDim.x)  g_cpack[528 + t] = r1[t];
        for (int t = threadIdx.x; t < 16; t += blockDim.x)  g_cpack[576 + t] = bs1[t];
        for (int t = threadIdx.x; t < 128; t += blockDim.x) g_cpack[592 + t] = r2[t];
        for (int t = threadIdx.x; t < 8; t += blockDim.x)   g_cpack[720 + t] = bs2[t];
    }
}

// Layer-1 edge scatter: 1 thread/edge, ONE red.v4 of (x[src], 1.0).
__global__ void scatter1(const int* __restrict__ src, const int* __restrict__ dst,
                         const int* __restrict__ et) {
    int e = blockIdx.x * blockDim.x + threadIdx.x;
    if (e >= EE) return;
    int r = et[e], s = src[e], d = dst[e];
    float4 v = __ldg(&g_x4[s]);
    red_add_v4(&g_sx[r * NN + d], v);
}

// Fused: layer-1 finalize + layer-2 dense (fp16 messages) + zero fp16 sums.
__global__ void fin1dense2() {
    int n = blockIdx.x * blockDim.x + threadIdx.x;
    if (n >= NN) return;
    float h[16];
    #pragma unroll
    for (int o = 0; o < 16; o++) h[o] = CB1(o);
    float4 xv = g_x4[n];
    float xi[3] = {xv.x, xv.y, xv.z};
    #pragma unroll
    for (int i = 0; i < 3; i++)
        #pragma unroll
        for (int o = 0; o < 16; o++) h[o] += xi[i] * CR1(i * 16 + o);
    #pragma unroll
    for (int r = 0; r < 3; r++) {
        float4 s = g_sx[r * NN + n];
        float inv = 1.0f / fmaxf(s.w, 1.0f);
        float m[3] = {s.x * inv, s.y * inv, s.z * inv};
        #pragma unroll
        for (int i = 0; i < 3; i++)
            #pragma unroll
            for (int o = 0; o < 16; o++) h[o] += m[i] * CW1(r * 48 + i * 16 + o);
    }
    #pragma unroll
    for (int o = 0; o < 16; o++) h[o] = fmaxf(h[o], 0.f);

    uint4 z = make_uint4(0u, 0u, 0u, 0u);
    #pragma unroll
    for (int r = 0; r < 3; r++) {
        float acc[8];
        #pragma unroll
        for (int c = 0; c < 8; c++) acc[c] = 0.f;
        #pragma unroll
        for (int k = 0; k < 16; k++)
            #pragma unroll
            for (int c = 0; c < 8; c++) acc[c] += h[k] * CW2(r * 128 + k * 8 + c);
        __half2 p0 = __float22half2_rn(make_float2(acc[0], acc[1]));
        __half2 p1 = __float22half2_rn(make_float2(acc[2], acc[3]));
        __half2 p2 = __float22half2_rn(make_float2(acc[4], acc[5]));
        __half2 p3 = __float22half2_rn(make_float2(acc[6], acc[7]));
        uint4 packed;
        packed.x = *reinterpret_cast<unsigned*>(&p0);
        packed.y = *reinterpret_cast<unsigned*>(&p1);
        packed.z = *reinterpret_cast<unsigned*>(&p2);
        packed.w = *reinterpret_cast<unsigned*>(&p3);
        g_xw2h[r * NN + n] = packed;
        g_sums2h[r * NN + n] = z;          // zero fp16 accumulator inline
    }
    float acc[8];
    #pragma unroll
    for (int c = 0; c < 8; c++) acc[c] = CB2(c);
    #pragma unroll
    for (int k = 0; k < 16; k++)
        #pragma unroll
        for (int c = 0; c < 8; c++) acc[c] += h[k] * CR2(k * 8 + c);
    g_rootx2[n * 2 + 0] = make_float4(acc[0], acc[1], acc[2], acc[3]);
    g_rootx2[n * 2 + 1] = make_float4(acc[4], acc[5], acc[6], acc[7]);
}

// Layer-2 edge scatter: 1 thread/edge, ONE 16B gather + ONE 16B fp16 RED.
// No conversion — message bits pass straight from LDG to RED.
__global__ void scatter2(const int* __restrict__ src, const int* __restrict__ dst,
                         const int* __restrict__ et) {
    int e = blockIdx.x * blockDim.x + threadIdx.x;
    if (e >= EE) return;
    int r = et[e], s = src[e], d = dst[e];
    uint4 p = __ldg(&g_xw2h[r * NN + s]);
    red_add_v4h2(&g_sums2h[r * NN + d], p);
}

// Layer-2 finalize + log_softmax. One thread per node. Counts from g_sx.w.
__global__ void finalize2(float* __restrict__ out) {
    int n = blockIdx.x * blockDim.x + threadIdx.x;
    if (n >= NN) return;
    float v[8];
    {
        float4 a = g_rootx2[n * 2 + 0], b = g_rootx2[n * 2 + 1];
        v[0]=a.x; v[1]=a.y; v[2]=a.z; v[3]=a.w;
        v[4]=b.x; v[5]=b.y; v[6]=b.z; v[7]=b.w;
    }
    #pragma unroll
    for (int r = 0; r < 3; r++) {
        float inv = 1.0f / fmaxf(g_sx[r * NN + n].w, 1.0f);
        uint4 p = g_sums2h[r * NN + n];
        float2 f0 = __half22float2(*reinterpret_cast<__half2*>(&p.x));
        float2 f1 = __half22float2(*reinterpret_cast<__half2*>(&p.y));
        float2 f2 = __half22float2(*reinterpret_cast<__half2*>(&p.z));
        float2 f3 = __half22float2(*reinterpret_cast<__half2*>(&p.w));
        v[0] += f0.x*inv; v[1] += f0.y*inv; v[2] += f1.x*inv; v[3] += f1.y*inv;
        v[4] += f2.x*inv; v[5] += f2.y*inv; v[6] += f3.x*inv; v[7] += f3.y*inv;
    }
    float m = v[0];
    #pragma unroll
    for (int i = 1; i < 8; i++) m = fmaxf(m, v[i]);
    float s = 0.f;
    #pragma unroll
    for (int i = 0; i < 8; i++) s += expf(v[i] - m);
    float lse = m + logf(s);
    float4* o = (float4*)(out + (size_t)n * 8);
    o[0] = make_float4(v[0]-lse, v[1]-lse, v[2]-lse, v[3]-lse);
    o[1] = make_float4(v[4]-lse, v[5]-lse, v[6]-lse, v[7]-lse);
}

// ---------------- host -------------------------------------------------------
extern "C" void kernel_launch(void* const* d_in, const int* in_sizes, int n_in,
                              void* d_out, int out_size) {
    const float *x = nullptr, *b1 = nullptr, *c1 = nullptr, *r1 = nullptr, *bs1 = nullptr;
    const float *b2 = nullptr, *c2 = nullptr, *r2 = nullptr, *bs2 = nullptr;
    const int *ei = nullptr, *et = nullptr;
    for (int i = 0; i < n_in; i++) {
        switch (in_sizes[i]) {
            case NN * 3:      x   = (const float*)d_in[i]; break;
            case 2 * EE:      ei  = (const int*)d_in[i];   break;
            case EE:          et  = (const int*)d_in[i];   break;
            case 5 * 3 * 16:  b1  = (const float*)d_in[i]; break;
            case 3 * 16:      r1  = (const float*)d_in[i]; break;
            case 16:          bs1 = (const float*)d_in[i]; break;
            case 5 * 16 * 8:  b2  = (const float*)d_in[i]; break;
            case 16 * 8:      r2  = (const float*)d_in[i]; break;
            case 8:           bs2 = (const float*)d_in[i]; break;
            case 15:          if (!c1) c1 = (const float*)d_in[i];
                              else     c2 = (const float*)d_in[i]; break;
            default: break;
        }
    }
    const int* src = ei;
    const int* dst = ei + EE;
    float* out = (float*)d_out;

    // Lazy resource creation (first call is uncaptured correctness run).
    static cudaStream_t s_side = nullptr;
    static cudaEvent_t  e_prep = nullptr, e_cpy = nullptr;
    static void* a_cpack = nullptr;
    if (!s_side) {
        cudaStreamCreateWithFlags(&s_side, cudaStreamNonBlocking);
        cudaEventCreateWithFlags(&e_prep, cudaEventDisableTiming);
        cudaEventCreateWithFlags(&e_cpy,  cudaEventDisableTiming);
        cudaGetSymbolAddress(&a_cpack, g_cpack);
    }

    const int T = 256;

    prep1<<<(NN + T - 1) / T, T>>>(x, b1, c1, b2, c2, r1, bs1, r2, bs2);

    // Single weight memcpy on side stream — hidden behind scatter1.
    cudaEventRecord(e_prep, 0);
    cudaStreamWaitEvent(s_side, e_prep, 0);
    cudaMemcpyToSymbolAsync(c_pack, a_cpack, 728 * sizeof(float), 0,
                            cudaMemcpyDeviceToDevice, s_side);
    cudaEventRecord(e_cpy, s_side);

    scatter1<<<EE / T, T>>>(src, dst, et);

    cudaStreamWaitEvent(0, e_cpy, 0);
    fin1dense2<<<(NN + T - 1) / T, T>>>();
    scatter2<<<EE / T, T>>>(src, dst, et);
    finalize2<<<(NN + T - 1) / T, T>>>(out);
    (void)out_size;
}

// round 9
// speedup vs baseline: 2.1536x; 1.0324x over previous
#include <cuda_runtime.h>
#include <cuda_fp16.h>
#include <cuda_bf16.h>

#define NN 200000
#define EE 6400000
// R=3, B=5, H=16, C=8

// ---------------- scratch ----------------------------------------------------
__device__ float4 g_x4    [NN];           // (x0, x1, x2, 1.0) per node
__device__ float4 g_sx    [3 * NN];       // per (r,dst): sum x + count in .w
__device__ uint4  g_xw2h  [3 * NN];       // [r][n][8] layer2 messages, fp16 (16B)
__device__ uint4  g_sums2h[3 * NN];       // per (r,dst) sums, layer2, fp16 (16B)
__device__ float4 g_rootx2[NN * 2];       // h@root2 + bias2
__device__ float  g_cpack [728];          // staging for all weights

// ---------------- constant weights (one packed bank, one memcpy) -------------
// Layout: W1[144] | W2[384] | root1[48] | bias1[16] | root2[128] | bias2[8]
__constant__ float c_pack[728];
#define CW1(i) c_pack[(i)]
#define CW2(i) c_pack[144 + (i)]
#define CR1(i) c_pack[528 + (i)]
#define CB1(i) c_pack[576 + (i)]
#define CR2(i) c_pack[592 + (i)]
#define CB2(i) c_pack[720 + (i)]

// ---------------- vectorized global reductions -------------------------------
__device__ __forceinline__ void red_add_v4(float4* addr, float4 v) {
    asm volatile("red.relaxed.gpu.global.add.v4.f32 [%0], {%1,%2,%3,%4};"
                 :: "l"(addr), "f"(v.x), "f"(v.y), "f"(v.z), "f"(v.w) : "memory");
}
__device__ __forceinline__ void red_add_v4h2(uint4* addr, uint4 v) {
    asm volatile("red.relaxed.gpu.global.add.noftz.v4.f16x2 [%0], {%1,%2,%3,%4};"
                 :: "l"(addr), "r"(v.x), "r"(v.y), "r"(v.z), "r"(v.w) : "memory");
}

// ---------------- kernels ----------------------------------------------------

// Fused prep: pack x, zero g_sx, build the full weight pack (block 0).
__global__ void prep1(const float* __restrict__ x,
                      const float* __restrict__ b1, const float* __restrict__ c1,
                      const float* __restrict__ b2, const float* __restrict__ c2,
                      const float* __restrict__ r1, const float* __restrict__ bs1,
                      const float* __restrict__ r2, const float* __restrict__ bs2) {
    int n = blockIdx.x * blockDim.x + threadIdx.x;
    if (n < NN) {
        g_x4[n] = make_float4(x[n * 3 + 0], x[n * 3 + 1], x[n * 3 + 2], 1.0f);
        float4 z = make_float4(0.f, 0.f, 0.f, 0.f);
        g_sx[n] = z;
        g_sx[NN + n] = z;
        g_sx[2 * NN + n] = z;
    }
    if (blockIdx.x == 0) {
        for (int t = threadIdx.x; t < 144; t += blockDim.x) {  // W1: [r][i][o]
            int r = t / 48, rem = t % 48, i = rem / 16, o = rem % 16;
            float acc = 0.f;
            #pragma unroll
            for (int b = 0; b < 5; b++) acc += c1[r * 5 + b] * b1[(b * 3 + i) * 16 + o];
            g_cpack[t] = acc;
        }
        for (int t = threadIdx.x; t < 384; t += blockDim.x) {  // W2: [r][k][c]
            int r = t / 128, rem = t % 128, k = rem / 8, c = rem % 8;
            float acc = 0.f;
            #pragma unroll
            for (int b = 0; b < 5; b++) acc += c2[r * 5 + b] * b2[(b * 16 + k) * 8 + c];
            g_cpack[144 + t] = acc;
        }
        for (int t = threadIdx.x; t < 48; t += blockDim.x)  g_cpack[528 + t] = r1[t];
        for (int t = threadIdx.x; t < 16; t += blockDim.x)  g_cpack[576 + t] = bs1[t];
        for (int t = threadIdx.x; t < 128; t += blockDim.x) g_cpack[592 + t] = r2[t];
        for (int t = threadIdx.x; t < 8; t += blockDim.x)   g_cpack[720 + t] = bs2[t];
    }
}

// Layer-1 edge scatter: 4 edges/thread, int4 index loads, 4 gathers in flight.
__global__ void scatter1(const int4* __restrict__ src4, const int4* __restrict__ dst4,
                         const int4* __restrict__ et4) {
    int t = blockIdx.x * blockDim.x + threadIdx.x;
    if (t >= EE / 4) return;
    int4 s = src4[t], d = dst4[t], r = et4[t];
    // 4 independent gathers issued back-to-back (MLP=4).
    float4 v0 = __ldg(&g_x4[s.x]);
    float4 v1 = __ldg(&g_x4[s.y]);
    float4 v2 = __ldg(&g_x4[s.z]);
    float4 v3 = __ldg(&g_x4[s.w]);
    red_add_v4(&g_sx[r.x * NN + d.x], v0);
    red_add_v4(&g_sx[r.y * NN + d.y], v1);
    red_add_v4(&g_sx[r.z * NN + d.z], v2);
    red_add_v4(&g_sx[r.w * NN + d.w], v3);
}

// Fused: layer-1 finalize + layer-2 dense (fp16 messages) + zero fp16 sums.
__global__ void fin1dense2() {
    int n = blockIdx.x * blockDim.x + threadIdx.x;
    if (n >= NN) return;
    float h[16];
    #pragma unroll
    for (int o = 0; o < 16; o++) h[o] = CB1(o);
    float4 xv = g_x4[n];
    float xi[3] = {xv.x, xv.y, xv.z};
    #pragma unroll
    for (int i = 0; i < 3; i++)
        #pragma unroll
        for (int o = 0; o < 16; o++) h[o] += xi[i] * CR1(i * 16 + o);
    #pragma unroll
    for (int r = 0; r < 3; r++) {
        float4 s = g_sx[r * NN + n];
        float inv = 1.0f / fmaxf(s.w, 1.0f);
        float m[3] = {s.x * inv, s.y * inv, s.z * inv};
        #pragma unroll
        for (int i = 0; i < 3; i++)
            #pragma unroll
            for (int o = 0; o < 16; o++) h[o] += m[i] * CW1(r * 48 + i * 16 + o);
    }
    #pragma unroll
    for (int o = 0; o < 16; o++) h[o] = fmaxf(h[o], 0.f);

    uint4 z = make_uint4(0u, 0u, 0u, 0u);
    #pragma unroll
    for (int r = 0; r < 3; r++) {
        float acc[8];
        #pragma unroll
        for (int c = 0; c < 8; c++) acc[c] = 0.f;
        #pragma unroll
        for (int k = 0; k < 16; k++)
            #pragma unroll
            for (int c = 0; c < 8; c++) acc[c] += h[k] * CW2(r * 128 + k * 8 + c);
        __half2 p0 = __float22half2_rn(make_float2(acc[0], acc[1]));
        __half2 p1 = __float22half2_rn(make_float2(acc[2], acc[3]));
        __half2 p2 = __float22half2_rn(make_float2(acc[4], acc[5]));
        __half2 p3 = __float22half2_rn(make_float2(acc[6], acc[7]));
        uint4 packed;
        packed.x = *reinterpret_cast<unsigned*>(&p0);
        packed.y = *reinterpret_cast<unsigned*>(&p1);
        packed.z = *reinterpret_cast<unsigned*>(&p2);
        packed.w = *reinterpret_cast<unsigned*>(&p3);
        g_xw2h[r * NN + n] = packed;
        g_sums2h[r * NN + n] = z;          // zero fp16 accumulator inline
    }
    float acc[8];
    #pragma unroll
    for (int c = 0; c < 8; c++) acc[c] = CB2(c);
    #pragma unroll
    for (int k = 0; k < 16; k++)
        #pragma unroll
        for (int c = 0; c < 8; c++) acc[c] += h[k] * CR2(k * 8 + c);
    g_rootx2[n * 2 + 0] = make_float4(acc[0], acc[1], acc[2], acc[3]);
    g_rootx2[n * 2 + 1] = make_float4(acc[4], acc[5], acc[6], acc[7]);
}

// Layer-2 edge scatter: 4 edges/thread, int4 index loads, 4 gathers in flight.
__global__ void scatter2(const int4* __restrict__ src4, const int4* __restrict__ dst4,
                         const int4* __restrict__ et4) {
    int t = blockIdx.x * blockDim.x + threadIdx.x;
    if (t >= EE / 4) return;
    int4 s = src4[t], d = dst4[t], r = et4[t];
    uint4 p0 = __ldg(&g_xw2h[r.x * NN + s.x]);
    uint4 p1 = __ldg(&g_xw2h[r.y * NN + s.y]);
    uint4 p2 = __ldg(&g_xw2h[r.z * NN + s.z]);
    uint4 p3 = __ldg(&g_xw2h[r.w * NN + s.w]);
    red_add_v4h2(&g_sums2h[r.x * NN + d.x], p0);
    red_add_v4h2(&g_sums2h[r.y * NN + d.y], p1);
    red_add_v4h2(&g_sums2h[r.z * NN + d.z], p2);
    red_add_v4h2(&g_sums2h[r.w * NN + d.w], p3);
}

// Layer-2 finalize + log_softmax. One thread per node. Counts from g_sx.w.
__global__ void finalize2(float* __restrict__ out) {
    int n = blockIdx.x * blockDim.x + threadIdx.x;
    if (n >= NN) return;
    float v[8];
    {
        float4 a = g_rootx2[n * 2 + 0], b = g_rootx2[n * 2 + 1];
        v[0]=a.x; v[1]=a.y; v[2]=a.z; v[3]=a.w;
        v[4]=b.x; v[5]=b.y; v[6]=b.z; v[7]=b.w;
    }
    #pragma unroll
    for (int r = 0; r < 3; r++) {
        float inv = 1.0f / fmaxf(g_sx[r * NN + n].w, 1.0f);
        uint4 p = g_sums2h[r * NN + n];
        float2 f0 = __half22float2(*reinterpret_cast<__half2*>(&p.x));
        float2 f1 = __half22float2(*reinterpret_cast<__half2*>(&p.y));
        float2 f2 = __half22float2(*reinterpret_cast<__half2*>(&p.z));
        float2 f3 = __half22float2(*reinterpret_cast<__half2*>(&p.w));
        v[0] += f0.x*inv; v[1] += f0.y*inv; v[2] += f1.x*inv; v[3] += f1.y*inv;
        v[4] += f2.x*inv; v[5] += f2.y*inv; v[6] += f3.x*inv; v[7] += f3.y*inv;
    }
    float m = v[0];
    #pragma unroll
    for (int i = 1; i < 8; i++) m = fmaxf(m, v[i]);
    float s = 0.f;
    #pragma unroll
    for (int i = 0; i < 8; i++) s += expf(v[i] - m);
    float lse = m + logf(s);
    float4* o = (float4*)(out + (size_t)n * 8);
    o[0] = make_float4(v[0]-lse, v[1]-lse, v[2]-lse, v[3]-lse);
    o[1] = make_float4(v[4]-lse, v[5]-lse, v[6]-lse, v[7]-lse);
}

// ---------------- host -------------------------------------------------------
extern "C" void kernel_launch(void* const* d_in, const int* in_sizes, int n_in,
                              void* d_out, int out_size) {
    const float *x = nullptr, *b1 = nullptr, *c1 = nullptr, *r1 = nullptr, *bs1 = nullptr;
    const float *b2 = nullptr, *c2 = nullptr, *r2 = nullptr, *bs2 = nullptr;
    const int *ei = nullptr, *et = nullptr;
    for (int i = 0; i < n_in; i++) {
        switch (in_sizes[i]) {
            case NN * 3:      x   = (const float*)d_in[i]; break;
            case 2 * EE:      ei  = (const int*)d_in[i];   break;
            case EE:          et  = (const int*)d_in[i];   break;
            case 5 * 3 * 16:  b1  = (const float*)d_in[i]; break;
            case 3 * 16:      r1  = (const float*)d_in[i]; break;
            case 16:          bs1 = (const float*)d_in[i]; break;
            case 5 * 16 * 8:  b2  = (const float*)d_in[i]; break;
            case 16 * 8:      r2  = (const float*)d_in[i]; break;
            case 8:           bs2 = (const float*)d_in[i]; break;
            case 15:          if (!c1) c1 = (const float*)d_in[i];
                              else     c2 = (const float*)d_in[i]; break;
            default: break;
        }
    }
    const int4* src4 = (const int4*)ei;
    const int4* dst4 = (const int4*)(ei + EE);
    const int4* et4  = (const int4*)et;
    float* out = (float*)d_out;

    // Lazy resource creation (first call is uncaptured correctness run).
    static cudaStream_t s_side = nullptr;
    static cudaEvent_t  e_prep = nullptr, e_cpy = nullptr;
    static void* a_cpack = nullptr;
    if (!s_side) {
        cudaStreamCreateWithFlags(&s_side, cudaStreamNonBlocking);
        cudaEventCreateWithFlags(&e_prep, cudaEventDisableTiming);
        cudaEventCreateWithFlags(&e_cpy,  cudaEventDisableTiming);
        cudaGetSymbolAddress(&a_cpack, g_cpack);
    }

    const int T = 256;

    prep1<<<(NN + T - 1) / T, T>>>(x, b1, c1, b2, c2, r1, bs1, r2, bs2);

    // Single weight memcpy on side stream — hidden behind scatter1.
    cudaEventRecord(e_prep, 0);
    cudaStreamWaitEvent(s_side, e_prep, 0);
    cudaMemcpyToSymbolAsync(c_pack, a_cpack, 728 * sizeof(float), 0,
                            cudaMemcpyDeviceToDevice, s_side);
    cudaEventRecord(e_cpy, s_side);

    scatter1<<<(EE / 4) / T, T>>>(src4, dst4, et4);

    cudaStreamWaitEvent(0, e_cpy, 0);
    fin1dense2<<<(NN + T - 1) / T, T>>>();
    scatter2<<<(EE / 4) / T, T>>>(src4, dst4, et4);
    finalize2<<<(NN + T - 1) / T, T>>>(out);
    (void)out_size;
}